// round 1
// baseline (speedup 1.0000x reference)
#include <cuda_runtime.h>
#include <cuda_bf16.h>

#define NN 50000
#define EE 1600000
#define CC 48
#define SS 10

// Scratch (allocation-free: __device__ globals)
__device__ float g_deg[NN];
__device__ float g_norm[EE];
__device__ float g_hA[NN * CC];
__device__ float g_hB[NN * CC];

// ---------------- degree accumulation ----------------
__global__ void deg_kernel(const int* __restrict__ ei, const float* __restrict__ ea) {
    int e = blockIdx.x * blockDim.x + threadIdx.x;
    if (e < EE) {
        atomicAdd(&g_deg[ei[e]], ea[e]);
    }
}

// ---------------- edge normalization ----------------
__global__ void norm_kernel(const int* __restrict__ ei, const float* __restrict__ ea) {
    int e = blockIdx.x * blockDim.x + threadIdx.x;
    if (e < EE) {
        float d = g_deg[ei[e]];
        g_norm[e] = ea[e] / fmaxf(d, 1e-12f);
    }
}

// ---------------- one-hot init (hA assumed zeroed) ----------------
__global__ void onehot_kernel(const int* __restrict__ target) {
    int n = blockIdx.x * blockDim.x + threadIdx.x;
    if (n < NN) {
        g_hA[n * CC + target[n]] = 1.0f;
    }
}

// ---------------- SpMM scatter step ----------------
// 12 threads per edge, each owns one float4 chunk of the 48-float row.
// blockDim = 192 -> 16 edges per block.
__global__ void spmm_kernel(const int* __restrict__ ei,
                            const float* __restrict__ hsrc,
                            float* __restrict__ hdst) {
    int e = blockIdx.x * 16 + threadIdx.x / 12;
    int c4 = threadIdx.x % 12;
    if (e < EE) {
        int r = ei[e];
        int c = ei[EE + e];
        float p = g_norm[e];
        const float4* src = reinterpret_cast<const float4*>(hsrc + r * CC) + c4;
        float4 v = __ldg(src);
        v.x *= p; v.y *= p; v.z *= p; v.w *= p;
        float4* dst = reinterpret_cast<float4*>(hdst + c * CC) + c4;
        asm volatile("red.global.add.v4.f32 [%0], {%1,%2,%3,%4};"
                     :: "l"(dst), "f"(v.x), "f"(v.y), "f"(v.z), "f"(v.w)
                     : "memory");
    }
}

// ---------------- weighted accumulate: out += h * w[:, s] ----------------
__global__ void axpy_kernel(float* __restrict__ out,
                            const float* __restrict__ h,
                            const float* __restrict__ weight,
                            int s) {
    int i = blockIdx.x * blockDim.x + threadIdx.x;
    if (i < NN * CC) {
        int c = i % CC;
        out[i] += h[i] * weight[c * SS + s];
    }
}

extern "C" void kernel_launch(void* const* d_in, const int* in_sizes, int n_in,
                              void* d_out, int out_size) {
    const int*   ei     = (const int*)d_in[0];    // [2, E]
    const float* ea     = (const float*)d_in[1];  // [E]
    const int*   target = (const int*)d_in[2];    // [N]
    const float* weight = (const float*)d_in[3];  // [C, S]
    float* out = (float*)d_out;                   // [N, C]

    void* p_deg;  cudaGetSymbolAddress(&p_deg,  g_deg);
    void* p_hA;   cudaGetSymbolAddress(&p_hA,   g_hA);
    void* p_hB;   cudaGetSymbolAddress(&p_hB,   g_hB);

    // 1) degree
    cudaMemsetAsync(p_deg, 0, NN * sizeof(float), 0);
    deg_kernel<<<(EE + 255) / 256, 256>>>(ei, ea);
    // 2) normalize
    norm_kernel<<<(EE + 255) / 256, 256>>>(ei, ea);
    // 3) h0 one-hot
    cudaMemsetAsync(p_hA, 0, (size_t)NN * CC * sizeof(float), 0);
    onehot_kernel<<<(NN + 255) / 256, 256>>>(target);
    // 4) out = 0
    cudaMemsetAsync(out, 0, (size_t)NN * CC * sizeof(float), 0);

    float* hcur = (float*)p_hA;
    float* hnxt = (float*)p_hB;
    const int spmm_blocks = (EE + 15) / 16;
    const int nc_blocks = (NN * CC + 255) / 256;

    for (int s = 0; s < SS; s++) {
        cudaMemsetAsync(hnxt, 0, (size_t)NN * CC * sizeof(float), 0);
        spmm_kernel<<<spmm_blocks, 192>>>(ei, hcur, hnxt);
        axpy_kernel<<<nc_blocks, 256>>>(out, hnxt, weight, s);
        float* t = hcur; hcur = hnxt; hnxt = t;
    }
}

// round 6
// speedup vs baseline: 1.9832x; 1.9832x over previous
#include <cuda_runtime.h>
#include <cuda_bf16.h>

#define NN 50000
#define EE 1600000
#define CC 48
#define SS 10

// Scratch (allocation-free: __device__ globals)
__device__ float  g_deg[NN];
__device__ int    g_cnt[NN];
__device__ int    g_off[NN + 1];
__device__ int    g_pos[NN];
__device__ float2 g_csc[EE];        // {src_as_float, p}
__device__ float  g_hA[NN * CC];
__device__ float  g_hB[NN * CC];

// ---------- pass 1: src-degree (for norm) + dst-count (for CSC) ----------
__global__ void count_deg_kernel(const int* __restrict__ ei,
                                 const float* __restrict__ ea) {
    int e = blockIdx.x * blockDim.x + threadIdx.x;
    if (e < EE) {
        atomicAdd(&g_deg[ei[e]], ea[e]);      // row = source
        atomicAdd(&g_cnt[ei[EE + e]], 1);     // col = dest
    }
}

// ---------- pass 2: single-block exclusive scan of g_cnt -> g_off/g_pos ----------
__global__ void scan_kernel() {
    __shared__ int warp_sums[32];
    __shared__ int s_carry;
    int tid = threadIdx.x;
    int lane = tid & 31, wid = tid >> 5;
    if (tid == 0) s_carry = 0;
    __syncthreads();

    for (int base = 0; base < NN; base += 1024) {
        int i = base + tid;
        int v = (i < NN) ? g_cnt[i] : 0;
        // warp inclusive scan
        int x = v;
        #pragma unroll
        for (int o = 1; o < 32; o <<= 1) {
            int y = __shfl_up_sync(0xFFFFFFFF, x, o);
            if (lane >= o) x += y;
        }
        if (lane == 31) warp_sums[wid] = x;
        __syncthreads();
        if (wid == 0) {
            int w = (lane < 32) ? warp_sums[lane] : 0;
            #pragma unroll
            for (int o = 1; o < 32; o <<= 1) {
                int y = __shfl_up_sync(0xFFFFFFFF, w, o);
                if (lane >= o) w += y;
            }
            warp_sums[lane] = w;
        }
        __syncthreads();
        int incl = x + (wid > 0 ? warp_sums[wid - 1] : 0);
        int excl = incl - v;
        int carry = s_carry;
        if (i < NN) {
            g_off[i] = carry + excl;
            g_pos[i] = carry + excl;
        }
        __syncthreads();
        if (tid == 1023) s_carry = carry + warp_sums[31];
        __syncthreads();
    }
    if (tid == 0) g_off[NN] = s_carry;
}

// ---------- pass 3: build CSC (norm folded in) ----------
__global__ void build_csc_kernel(const int* __restrict__ ei,
                                 const float* __restrict__ ea) {
    int e = blockIdx.x * blockDim.x + threadIdx.x;
    if (e < EE) {
        int r = ei[e];
        int c = ei[EE + e];
        float p = ea[e] / fmaxf(g_deg[r], 1e-12f);
        int pos = atomicAdd(&g_pos[c], 1);
        g_csc[pos] = make_float2(__int_as_float(r), p);
    }
}

// ---------- step 0: h0 is one-hot(target); gather target[src] directly ----------
// 12 threads per node, each owns channels [c4*4, c4*4+4)
__global__ void step0_kernel(const int* __restrict__ target,
                             float* __restrict__ hdst,
                             float* __restrict__ out,
                             const float* __restrict__ weight) {
    int node = blockIdx.x * 16 + threadIdx.x / 12;
    int c4 = threadIdx.x % 12;
    if (node >= NN) return;
    int beg = g_off[node], end = g_off[node + 1];
    int cbase = c4 * 4;
    float4 acc = make_float4(0.f, 0.f, 0.f, 0.f);
    for (int j = beg; j < end; j++) {
        float2 ed = __ldg(&g_csc[j]);
        int src = __float_as_int(ed.x);
        float p = ed.y;
        int tc = __ldg(&target[src]);
        acc.x += (tc == cbase + 0) ? p : 0.f;
        acc.y += (tc == cbase + 1) ? p : 0.f;
        acc.z += (tc == cbase + 2) ? p : 0.f;
        acc.w += (tc == cbase + 3) ? p : 0.f;
    }
    reinterpret_cast<float4*>(hdst + node * CC)[c4] = acc;
    float w0 = __ldg(&weight[(cbase + 0) * SS]);
    float w1 = __ldg(&weight[(cbase + 1) * SS]);
    float w2 = __ldg(&weight[(cbase + 2) * SS]);
    float w3 = __ldg(&weight[(cbase + 3) * SS]);
    float4 o;
    o.x = acc.x * w0; o.y = acc.y * w1; o.z = acc.z * w2; o.w = acc.w * w3;
    reinterpret_cast<float4*>(out + node * CC)[c4] = o;   // first write: no read needed
}

// ---------- steps 1..9: CSC gather SpMM with fused weighted accumulate ----------
__global__ void gather_kernel(const float* __restrict__ hsrc,
                              float* __restrict__ hdst,
                              float* __restrict__ out,
                              const float* __restrict__ weight,
                              int s) {
    int node = blockIdx.x * 16 + threadIdx.x / 12;
    int c4 = threadIdx.x % 12;
    if (node >= NN) return;
    int beg = g_off[node], end = g_off[node + 1];
    float4 acc = make_float4(0.f, 0.f, 0.f, 0.f);
    for (int j = beg; j < end; j++) {
        float2 ed = __ldg(&g_csc[j]);
        int src = __float_as_int(ed.x);
        float p = ed.y;
        float4 v = __ldg(reinterpret_cast<const float4*>(hsrc + src * CC) + c4);
        acc.x += p * v.x;
        acc.y += p * v.y;
        acc.z += p * v.z;
        acc.w += p * v.w;
    }
    reinterpret_cast<float4*>(hdst + node * CC)[c4] = acc;
    int cbase = c4 * 4;
    float w0 = __ldg(&weight[(cbase + 0) * SS + s]);
    float w1 = __ldg(&weight[(cbase + 1) * SS + s]);
    float w2 = __ldg(&weight[(cbase + 2) * SS + s]);
    float w3 = __ldg(&weight[(cbase + 3) * SS + s]);
    float4 o = reinterpret_cast<float4*>(out + node * CC)[c4];
    o.x += acc.x * w0; o.y += acc.y * w1; o.z += acc.z * w2; o.w += acc.w * w3;
    reinterpret_cast<float4*>(out + node * CC)[c4] = o;
}

extern "C" void kernel_launch(void* const* d_in, const int* in_sizes, int n_in,
                              void* d_out, int out_size) {
    const int*   ei     = (const int*)d_in[0];    // [2, E]
    const float* ea     = (const float*)d_in[1];  // [E]
    const int*   target = (const int*)d_in[2];    // [N]
    const float* weight = (const float*)d_in[3];  // [C, S]
    float* out = (float*)d_out;                   // [N, C]

    void* p_deg; cudaGetSymbolAddress(&p_deg, g_deg);
    void* p_cnt; cudaGetSymbolAddress(&p_cnt, g_cnt);
    void* p_hA;  cudaGetSymbolAddress(&p_hA,  g_hA);
    void* p_hB;  cudaGetSymbolAddress(&p_hB,  g_hB);

    cudaMemsetAsync(p_deg, 0, NN * sizeof(float), 0);
    cudaMemsetAsync(p_cnt, 0, NN * sizeof(int), 0);

    count_deg_kernel<<<(EE + 255) / 256, 256>>>(ei, ea);
    scan_kernel<<<1, 1024>>>();
    build_csc_kernel<<<(EE + 255) / 256, 256>>>(ei, ea);

    float* hA = (float*)p_hA;
    float* hB = (float*)p_hB;
    const int node_blocks = (NN + 15) / 16;

    // step 0 (one-hot fast path) writes h1 into hA and initializes out
    step0_kernel<<<node_blocks, 192>>>(target, hA, out, weight);

    float* hcur = hA;
    float* hnxt = hB;
    for (int s = 1; s < SS; s++) {
        gather_kernel<<<node_blocks, 192>>>(hcur, hnxt, out, weight, s);
        float* t = hcur; hcur = hnxt; hnxt = t;
    }
}

// round 9
// speedup vs baseline: 2.4491x; 1.2349x over previous
#include <cuda_runtime.h>
#include <cuda_fp16.h>

#define NN 50000
#define EE 1600000
#define CC 48
#define SS 10

// Scratch (allocation-free: __device__ globals)
__device__ float  g_deg[NN];
__device__ int    g_cnt[NN];
__device__ int    g_off[NN + 4];     // padded for int4 stores
__device__ int    g_pos[NN];
__device__ float2 g_csc[EE];         // {src_as_float, p}
__device__ __half g_hA[NN * CC];     // fp16 feature rows (96 B/row)
__device__ __half g_hB[NN * CC];

// ---------- pass 1: src-degree (for norm) + dst-count (for CSC) ----------
__global__ void count_deg_kernel(const int* __restrict__ ei,
                                 const float* __restrict__ ea) {
    int e = blockIdx.x * blockDim.x + threadIdx.x;
    if (e < EE) {
        atomicAdd(&g_deg[ei[e]], ea[e]);      // row = source
        atomicAdd(&g_cnt[ei[EE + e]], 1);     // col = dest
    }
}

// ---------- pass 2: single-block exclusive scan, 4 elems/thread ----------
__global__ void scan_kernel() {
    __shared__ int warp_sums[32];
    __shared__ int s_carry;
    int tid = threadIdx.x;
    int lane = tid & 31, wid = tid >> 5;
    if (tid == 0) s_carry = 0;
    __syncthreads();

    // NN = 50000 is divisible by 4 -> each int4 chunk is fully in or out of range
    for (int base = 0; base < NN; base += 4096) {
        int idx = base + tid * 4;
        int4 v = make_int4(0, 0, 0, 0);
        if (idx < NN) v = reinterpret_cast<const int4*>(g_cnt)[idx >> 2];
        int s0 = v.x;
        int s01 = s0 + v.y;
        int s012 = s01 + v.z;
        int tot = s012 + v.w;
        // warp inclusive scan of tot
        int x = tot;
        #pragma unroll
        for (int o = 1; o < 32; o <<= 1) {
            int y = __shfl_up_sync(0xFFFFFFFF, x, o);
            if (lane >= o) x += y;
        }
        if (lane == 31) warp_sums[wid] = x;
        __syncthreads();
        if (wid == 0) {
            int w = warp_sums[lane];
            #pragma unroll
            for (int o = 1; o < 32; o <<= 1) {
                int y = __shfl_up_sync(0xFFFFFFFF, w, o);
                if (lane >= o) w += y;
            }
            warp_sums[lane] = w;
        }
        __syncthreads();
        int excl = x - tot + (wid > 0 ? warp_sums[wid - 1] : 0);
        int e0 = s_carry + excl;
        if (idx < NN) {
            int4 outs = make_int4(e0, e0 + s0, e0 + s01, e0 + s012);
            reinterpret_cast<int4*>(g_off)[idx >> 2] = outs;
            reinterpret_cast<int4*>(g_pos)[idx >> 2] = outs;
        }
        __syncthreads();
        if (tid == 1023) s_carry += warp_sums[31];
        __syncthreads();
    }
    if (tid == 0) g_off[NN] = s_carry;
}

// ---------- pass 3: build CSC (norm folded in) ----------
__global__ void build_csc_kernel(const int* __restrict__ ei,
                                 const float* __restrict__ ea) {
    int e = blockIdx.x * blockDim.x + threadIdx.x;
    if (e < EE) {
        int r = ei[e];
        int c = ei[EE + e];
        float p = ea[e] / fmaxf(g_deg[r], 1e-12f);
        int pos = atomicAdd(&g_pos[c], 1);
        g_csc[pos] = make_float2(__int_as_float(r), p);
    }
}

__device__ __forceinline__ uint2 pack_half4(float4 a) {
    uint2 o;
    __half2 lo = __float22half2_rn(make_float2(a.x, a.y));
    __half2 hi = __float22half2_rn(make_float2(a.z, a.w));
    o.x = *reinterpret_cast<unsigned*>(&lo);
    o.y = *reinterpret_cast<unsigned*>(&hi);
    return o;
}

// ---------- step 0: h0 one-hot(target); gather target[src] directly ----------
// 12 threads per node, thread c4 owns channels [c4*4, c4*4+4)
__global__ void step0_kernel(const int* __restrict__ target,
                             __half* __restrict__ hdst,
                             float* __restrict__ out,
                             const float* __restrict__ weight) {
    int node = blockIdx.x * 16 + threadIdx.x / 12;
    int c4 = threadIdx.x % 12;
    if (node >= NN) return;
    int beg = g_off[node], end = g_off[node + 1];
    int cbase = c4 * 4;
    float4 acc = make_float4(0.f, 0.f, 0.f, 0.f);
    for (int j = beg; j < end; j++) {
        float2 ed = __ldg(&g_csc[j]);
        int src = __float_as_int(ed.x);
        float p = ed.y;
        int tc = __ldg(&target[src]);
        acc.x += (tc == cbase + 0) ? p : 0.f;
        acc.y += (tc == cbase + 1) ? p : 0.f;
        acc.z += (tc == cbase + 2) ? p : 0.f;
        acc.w += (tc == cbase + 3) ? p : 0.f;
    }
    reinterpret_cast<uint2*>(hdst + node * CC)[c4] = pack_half4(acc);
    float w0 = __ldg(&weight[(cbase + 0) * SS]);
    float w1 = __ldg(&weight[(cbase + 1) * SS]);
    float w2 = __ldg(&weight[(cbase + 2) * SS]);
    float w3 = __ldg(&weight[(cbase + 3) * SS]);
    float4 o;
    o.x = acc.x * w0; o.y = acc.y * w1; o.z = acc.z * w2; o.w = acc.w * w3;
    reinterpret_cast<float4*>(out + node * CC)[c4] = o;   // first write: no read needed
}

// ---------- steps 1..9: fp16 CSC gather SpMM, fp32 accumulate, fused axpy ----------
__global__ void gather_kernel(const __half* __restrict__ hsrc,
                              __half* __restrict__ hdst,
                              float* __restrict__ out,
                              const float* __restrict__ weight,
                              int s, int write_h) {
    int node = blockIdx.x * 16 + threadIdx.x / 12;
    int c4 = threadIdx.x % 12;
    if (node >= NN) return;
    int beg = g_off[node], end = g_off[node + 1];
    float4 acc = make_float4(0.f, 0.f, 0.f, 0.f);
    for (int j = beg; j < end; j++) {
        float2 ed = __ldg(&g_csc[j]);
        int src = __float_as_int(ed.x);
        float p = ed.y;
        uint2 raw = __ldg(reinterpret_cast<const uint2*>(hsrc + src * CC) + c4);
        __half2 h0 = *reinterpret_cast<__half2*>(&raw.x);
        __half2 h1 = *reinterpret_cast<__half2*>(&raw.y);
        float2 fa = __half22float2(h0);
        float2 fb = __half22float2(h1);
        acc.x = fmaf(p, fa.x, acc.x);
        acc.y = fmaf(p, fa.y, acc.y);
        acc.z = fmaf(p, fb.x, acc.z);
        acc.w = fmaf(p, fb.y, acc.w);
    }
    if (write_h)
        reinterpret_cast<uint2*>(hdst + node * CC)[c4] = pack_half4(acc);
    int cbase = c4 * 4;
    float w0 = __ldg(&weight[(cbase + 0) * SS + s]);
    float w1 = __ldg(&weight[(cbase + 1) * SS + s]);
    float w2 = __ldg(&weight[(cbase + 2) * SS + s]);
    float w3 = __ldg(&weight[(cbase + 3) * SS + s]);
    float4 o = reinterpret_cast<float4*>(out + node * CC)[c4];
    o.x += acc.x * w0; o.y += acc.y * w1; o.z += acc.z * w2; o.w += acc.w * w3;
    reinterpret_cast<float4*>(out + node * CC)[c4] = o;
}

extern "C" void kernel_launch(void* const* d_in, const int* in_sizes, int n_in,
                              void* d_out, int out_size) {
    const int*   ei     = (const int*)d_in[0];    // [2, E]
    const float* ea     = (const float*)d_in[1];  // [E]
    const int*   target = (const int*)d_in[2];    // [N]
    const float* weight = (const float*)d_in[3];  // [C, S]
    float* out = (float*)d_out;                   // [N, C]

    void* p_deg; cudaGetSymbolAddress(&p_deg, g_deg);
    void* p_cnt; cudaGetSymbolAddress(&p_cnt, g_cnt);
    void* p_hA;  cudaGetSymbolAddress(&p_hA,  g_hA);
    void* p_hB;  cudaGetSymbolAddress(&p_hB,  g_hB);

    cudaMemsetAsync(p_deg, 0, NN * sizeof(float), 0);
    cudaMemsetAsync(p_cnt, 0, NN * sizeof(int), 0);

    count_deg_kernel<<<(EE + 255) / 256, 256>>>(ei, ea);
    scan_kernel<<<1, 1024>>>();
    build_csc_kernel<<<(EE + 255) / 256, 256>>>(ei, ea);

    __half* hA = (__half*)p_hA;
    __half* hB = (__half*)p_hB;
    const int node_blocks = (NN + 15) / 16;

    // step 0 (one-hot fast path) writes h1 into hA and initializes out
    step0_kernel<<<node_blocks, 192>>>(target, hA, out, weight);

    __half* hcur = hA;
    __half* hnxt = hB;
    for (int s = 1; s < SS; s++) {
        gather_kernel<<<node_blocks, 192>>>(hcur, hnxt, out, weight, s,
                                            (s < SS - 1) ? 1 : 0);
        __half* t = hcur; hcur = hnxt; hnxt = t;
    }
}